// round 11
// baseline (speedup 1.0000x reference)
#include <cuda_runtime.h>
#include <cstdint>

#define N_NODES 20000
#define N_EDGES 320000

typedef unsigned long long u64;

// ---------------- device scratch -----------------------------------------------
__device__ __align__(16) float g_h[N_NODES * 64];              // h = nf@w_up/8
__device__ __align__(16) float g_agg[(size_t)N_NODES * 576];   // m-major planes
__device__ __align__(16) uint32_t g_wsplit[22592];             // pre-split MLP weights

// ---------------- helpers -------------------------------------------------------
__device__ __forceinline__ uint32_t packbf(float lo, float hi) {
    uint32_t d; asm("cvt.rn.bf16x2.f32 %0, %1, %2;" : "=r"(d) : "f"(hi), "f"(lo));
    return d;
}
// split (v0,v1) -> (hi bf16x2, lo bf16x2), v0 in low half
__device__ __forceinline__ uint2 split_pair(float v0, float v1) {
    uint32_t h = packbf(v0, v1);
    float l0 = v0 - __uint_as_float(h << 16);
    float l1 = v1 - __uint_as_float(h & 0xFFFF0000u);
    return make_uint2(h, packbf(l0, l1));
}
__device__ __forceinline__ void red4(float* p, float a, float b, float c, float d) {
    asm volatile("red.global.add.v4.f32 [%0], {%1, %2, %3, %4};"
                 :: "l"((u64)__cvta_generic_to_global(p)),
                    "f"(a), "f"(b), "f"(c), "f"(d) : "memory");
}
#define MMA16(C, a0, a1, a2, a3, b0, b1) \
    asm volatile("mma.sync.aligned.m16n8k16.row.col.f32.bf16.bf16.f32 " \
        "{%0,%1,%2,%3}, {%4,%5,%6,%7}, {%8,%9}, {%0,%1,%2,%3};" \
        : "+f"((C)[0]), "+f"((C)[1]), "+f"((C)[2]), "+f"((C)[3]) \
        : "r"(a0), "r"(a1), "r"(a2), "r"(a3), "r"(b0), "r"(b1))
#define MMA8B(C, a0, a1, b0) \
    asm volatile("mma.sync.aligned.m16n8k8.row.col.f32.bf16.bf16.f32 " \
        "{%0,%1,%2,%3}, {%4,%5}, {%6}, {%0,%1,%2,%3};" \
        : "+f"((C)[0]), "+f"((C)[1]), "+f"((C)[2]), "+f"((C)[3]) \
        : "r"(a0), "r"(a1), "r"(b0))

// 3-term bf16-split MMA over K=64 from register A-fragments, smem weights.
__device__ __forceinline__ void mma_layer_reg(const uint32_t* __restrict__ aH,
                                              const uint32_t* __restrict__ aL,
                                              const uint32_t* __restrict__ wHi,
                                              const uint32_t* __restrict__ wLo,
                                              int ws, int nbase, float C[8][4],
                                              int lane) {
    const int g = lane >> 2, q = lane & 3;
#pragma unroll
    for (int nt = 0; nt < 8; nt++)
        C[nt][0] = C[nt][1] = C[nt][2] = C[nt][3] = 0.f;
#pragma unroll
    for (int kt = 0; kt < 4; kt++) {
        uint32_t ah0 = aH[kt * 4 + 0], ah1 = aH[kt * 4 + 1];
        uint32_t ah2 = aH[kt * 4 + 2], ah3 = aH[kt * 4 + 3];
        uint32_t al0 = aL[kt * 4 + 0], al1 = aL[kt * 4 + 1];
        uint32_t al2 = aL[kt * 4 + 2], al3 = aL[kt * 4 + 3];
        const int b0r = (kt * 8 + q) * ws;
        const int b1r = (kt * 8 + 4 + q) * ws;
#pragma unroll
        for (int nt = 0; nt < 8; nt++) {
            const int n = nbase + nt * 8 + g;
            uint32_t bh0 = wHi[b0r + n], bh1 = wHi[b1r + n];
            uint32_t bl0 = wLo[b0r + n], bl1 = wLo[b1r + n];
            MMA16(C[nt], ah0, ah1, ah2, ah3, bh0, bh1);
            MMA16(C[nt], ah0, ah1, ah2, ah3, bl0, bl1);
            MMA16(C[nt], al0, al1, al2, al3, bh0, bh1);
        }
    }
}

// ---------------- merged init kernel: zero agg + node_up + weight prep ----------
__device__ __forceinline__ void fill_dev(const float* __restrict__ w,
                                         uint32_t* __restrict__ dHi,
                                         uint32_t* __restrict__ dLo,
                                         int K2, int N, int ws, int t) {
    for (int i = t; i < K2 * N; i += 256) {
        int k2 = i / N, n = i - k2 * N;
        uint2 p = split_pair(w[(2 * k2) * N + n], w[(2 * k2 + 1) * N + n]);
        dHi[k2 * ws + n] = p.x;
        dLo[k2 * ws + n] = p.y;
    }
}

__global__ void __launch_bounds__(256) k_init(
    const float* __restrict__ nf, const float* __restrict__ wup,
    const float* __restrict__ w1, const float* __restrict__ w2,
    const float* __restrict__ w3, const float* __restrict__ w4) {
    __shared__ __align__(16) float sW[64 * 64];
    __shared__ float sA[32 * 65];
    const int b = blockIdx.x;
    const int t = threadIdx.x;

    if (b < 11250) {                       // zero 46MB of g_agg
        size_t i = (size_t)b * 256 + t;
        reinterpret_cast<float4*>(g_agg)[i] = make_float4(0.f, 0.f, 0.f, 0.f);
    } else if (b < 11875) {                // h = nf @ w_up * (1/8)
        const int nb = (b - 11250) * 32;
        for (int i = t; i < 4096; i += 256) sW[i] = wup[i];
        for (int i = t; i < 2048; i += 256) sA[(i >> 6) * 65 + (i & 63)] = nf[nb * 64 + i];
        __syncthreads();
        const int ty = t >> 4, tx = t & 15;
        const int r0 = ty * 2, c0 = tx * 4;
        float acc[2][4] = {};
#pragma unroll 8
        for (int k = 0; k < 64; k++) {
            float a0 = sA[r0 * 65 + k];
            float a1 = sA[(r0 + 1) * 65 + k];
            float4 bb = *reinterpret_cast<const float4*>(&sW[k * 64 + c0]);
            acc[0][0] += a0 * bb.x; acc[0][1] += a0 * bb.y; acc[0][2] += a0 * bb.z; acc[0][3] += a0 * bb.w;
            acc[1][0] += a1 * bb.x; acc[1][1] += a1 * bb.y; acc[1][2] += a1 * bb.z; acc[1][3] += a1 * bb.w;
        }
#pragma unroll
        for (int i = 0; i < 2; i++)
#pragma unroll
            for (int j = 0; j < 4; j++)
                g_h[(nb + r0 + i) * 64 + c0 + j] = acc[i][j] * 0.125f;
    } else {                               // pre-split MLP weights
        const int bb = b - 11875;
        if (bb == 0)      fill_dev(w1, g_wsplit,        g_wsplit + 288,   4,  64,  72,  t);
        else if (bb == 1) fill_dev(w2, g_wsplit + 576,  g_wsplit + 2880,  32, 64,  72,  t);
        else if (bb == 2) fill_dev(w3, g_wsplit + 5184, g_wsplit + 7488,  32, 64,  72,  t);
        else              fill_dev(w4, g_wsplit + 9792, g_wsplit + 16192, 32, 192, 200, t);
    }
}

// ---------------- fused register-dataflow bf16-split MLP + scatter --------------
// silu(scale*C) -> bf16 hi/lo A-fragments, all in registers.
__device__ __forceinline__ void act_frags(const float C[8][4], float scale,
                                          uint32_t* __restrict__ aH,
                                          uint32_t* __restrict__ aL) {
    float v[8][4];
#pragma unroll
    for (int nt = 0; nt < 8; nt++)
#pragma unroll
        for (int j = 0; j < 4; j++) {
            float x = C[nt][j] * scale;
            v[nt][j] = __fdividef(x, 1.f + __expf(-x));
        }
#pragma unroll
    for (int kt = 0; kt < 4; kt++) {
        uint2 p0 = split_pair(v[2 * kt][0],     v[2 * kt][1]);
        uint2 p1 = split_pair(v[2 * kt][2],     v[2 * kt][3]);
        uint2 p2 = split_pair(v[2 * kt + 1][0], v[2 * kt + 1][1]);
        uint2 p3 = split_pair(v[2 * kt + 1][2], v[2 * kt + 1][3]);
        aH[kt * 4 + 0] = p0.x; aL[kt * 4 + 0] = p0.y;
        aH[kt * 4 + 1] = p1.x; aL[kt * 4 + 1] = p1.y;
        aH[kt * 4 + 2] = p2.x; aL[kt * 4 + 2] = p2.y;
        aH[kt * 4 + 3] = p3.x; aL[kt * 4 + 3] = p3.y;
    }
}

__global__ void __launch_bounds__(256, 2) k_fused(
    const float* __restrict__ radial, const float* __restrict__ vectors,
    const int* __restrict__ senders, const int* __restrict__ receivers) {
    extern __shared__ __align__(16) uint32_t smu[];
    uint32_t* wHi1 = smu;            uint32_t* wLo1 = smu + 288;
    uint32_t* wHi2 = smu + 576;      uint32_t* wLo2 = smu + 2880;
    uint32_t* wHi3 = smu + 5184;     uint32_t* wLo3 = smu + 7488;
    uint32_t* wHi4 = smu + 9792;     uint32_t* wLo4 = smu + 16192;

    const int t    = threadIdx.x;
    const int warp = t >> 5;
    const int lane = t & 31;
    const int w16  = warp * 16;
    const int g = lane >> 2, q = lane & 3;

    // flat copy of pre-split weights (22592 u32 = 5648 uint4)
    {
        const uint4* src = reinterpret_cast<const uint4*>(g_wsplit);
        uint4*       dst = reinterpret_cast<uint4*>(smu);
        for (int i = t; i < 5648; i += 256) dst[i] = src[i];
    }

    // ---- hoisted edge loads: issue early, consume after layer 3 ----
    const int e0 = blockIdx.x * 128 + w16 + g;
    const int e1 = e0 + 8;
    const int snd0 = senders[e0], snd1 = senders[e1];
    const int rcv0 = receivers[e0], rcv1 = receivers[e1];
    float vxa = vectors[(size_t)e0 * 3 + 0];
    float vya = vectors[(size_t)e0 * 3 + 1];
    float vza = vectors[(size_t)e0 * 3 + 2];
    float vxb = vectors[(size_t)e1 * 3 + 0];
    float vyb = vectors[(size_t)e1 * 3 + 1];
    float vzb = vectors[(size_t)e1 * 3 + 2];

    __syncthreads();

    float C[8][4];
    uint32_t aH[16], aL[16];

    // ---- layer 1: radial[16,8] @ W1 (m16n8k8), scale 1/sqrt(8), silu ----
    {
        const float* rb = radial + (size_t)(blockIdx.x * 128 + w16) * 8;
        float2 q0 = *reinterpret_cast<const float2*>(rb + g * 8 + 2 * q);
        float2 q1 = *reinterpret_cast<const float2*>(rb + (g + 8) * 8 + 2 * q);
        uint2 a0 = split_pair(q0.x, q0.y);
        uint2 a1 = split_pair(q1.x, q1.y);
#pragma unroll
        for (int nt = 0; nt < 8; nt++) {
            C[nt][0] = C[nt][1] = C[nt][2] = C[nt][3] = 0.f;
            const int n = nt * 8 + g;
            uint32_t bh = wHi1[q * 72 + n];
            uint32_t bl = wLo1[q * 72 + n];
            MMA8B(C[nt], a0.x, a1.x, bh);
            MMA8B(C[nt], a0.x, a1.x, bl);
            MMA8B(C[nt], a0.y, a1.y, bh);
        }
        act_frags(C, 0.35355339059327373f, aH, aL);
    }

    // ---- layer 2 ----
    mma_layer_reg(aH, aL, wHi2, wLo2, 72, 0, C, lane);
    act_frags(C, 0.125f, aH, aL);

    // ---- h gathers: issue here so latency hides under layer 3 MMAs ----
    float2 hA[8], hB[8];
#pragma unroll
    for (int nt = 0; nt < 8; nt++) {
        hA[nt] = *reinterpret_cast<const float2*>(g_h + (size_t)snd0 * 64 + nt * 8 + 2 * q);
        hB[nt] = *reinterpret_cast<const float2*>(g_h + (size_t)snd1 * 64 + nt * 8 + 2 * q);
    }

    // ---- layer 3 ----
    mma_layer_reg(aH, aL, wHi3, wLo3, 72, 0, C, lane);
    act_frags(C, 0.125f, aH, aL);

    // ---- spherical harmonics + scatter setup ----
    float* aggA = g_agg + (size_t)rcv0 * 576;
    float* aggB = g_agg + (size_t)rcv1 * 576;
    float y1a[3], y2a[5], y1b[3], y2b[5];
    {
        float rn = rsqrtf(vxa * vxa + vya * vya + vza * vza);
        float x = vxa * rn, y = vya * rn, z = vza * rn;
        const float SQ3 = 1.7320508075688772f, S15 = 3.872983346207417f;
        y1a[0] = SQ3 * x; y1a[1] = SQ3 * y; y1a[2] = SQ3 * z;
        y2a[0] = S15 * x * y; y2a[1] = S15 * y * z;
        y2a[2] = 1.118033988749895f * (3.f * z * z - 1.f);
        y2a[3] = S15 * x * z; y2a[4] = 0.5f * S15 * (x * x - y * y);
    }
    {
        float rn = rsqrtf(vxb * vxb + vyb * vyb + vzb * vzb);
        float x = vxb * rn, y = vyb * rn, z = vzb * rn;
        const float SQ3 = 1.7320508075688772f, S15 = 3.872983346207417f;
        y1b[0] = SQ3 * x; y1b[1] = SQ3 * y; y1b[2] = SQ3 * z;
        y2b[0] = S15 * x * y; y2b[1] = S15 * y * z;
        y2b[2] = 1.118033988749895f * (3.f * z * z - 1.f);
        y2b[3] = S15 * x * z; y2b[4] = 0.5f * S15 * (x * x - y * y);
    }
    const float SCL = 0.0009765625f;   // 0.125 (w4 norm) * (1/64) * 0.5 (EPS)

    const bool odd  = (q & 1);
    const int  col4 = (q >> 1) * 4;
    float*       myAgg = odd ? aggB : aggA;

    // ---- layer 4: 3 segments, scatter via lane-pair exchange + red.v4 ----
#pragma unroll
    for (int seg = 0; seg < 3; seg++) {
        mma_layer_reg(aH, aL, wHi4, wLo4, 200, seg * 64, C, lane);
        const int NP  = (seg == 0) ? 1 : (seg == 1 ? 3 : 5);
        const int OFF = (seg == 0) ? 0 : (seg == 1 ? 64 : 256);
        const float* Yv = odd ? ((seg == 1) ? y1b : y2b) : ((seg == 1) ? y1a : y2a);
#pragma unroll
        for (int nt = 0; nt < 8; nt++) {
            float uA0 = C[nt][0] * hA[nt].x * SCL;
            float uA1 = C[nt][1] * hA[nt].y * SCL;
            float uB0 = C[nt][2] * hB[nt].x * SCL;
            float uB1 = C[nt][3] * hB[nt].y * SCL;
            float s0 = odd ? uA0 : uB0;
            float s1 = odd ? uA1 : uB1;
            float r0 = __shfl_xor_sync(0xFFFFFFFFu, s0, 1);
            float r1 = __shfl_xor_sync(0xFFFFFFFFu, s1, 1);
            float w0 = odd ? r0 : uA0;
            float w1 = odd ? r1 : uA1;
            float w2 = odd ? uB0 : r0;
            float w3 = odd ? uB1 : r1;
            float* base = myAgg + nt * 8 + col4;
            if (seg == 0) {
                red4(base, w0, w1, w2, w3);
            } else {
#pragma unroll
                for (int p = 0; p < 5; p++) {
                    if (p < NP) {
                        float yp = Yv[p];
                        red4(base + OFF + p * 64, w0 * yp, w1 * yp, w2 * yp, w3 * yp);
                    }
                }
            }
        }
    }
}

// ---------------- kernel 4: tensor-core down-projection -------------------------
// grid (157, 3): x = 128-node tile (8 warps x m16), y = l-group.
// A = agg rows loaded as float2, split to bf16 hi/lo in registers; W pre-split
// into smem (ws=72, conflict-free). Outputs written from C-fragments.
__global__ void __launch_bounds__(256) k_down(const float* __restrict__ w0,
                                              const float* __restrict__ w1,
                                              const float* __restrict__ w2,
                                              float* __restrict__ out) {
    __shared__ __align__(16) uint32_t sWd[2 * 2304];   // hi @0, lo @2304

    const int t    = threadIdx.x;
    const int warp = t >> 5;
    const int lane = t & 31;
    const int g = lane >> 2, q = lane & 3;
    const int seg = blockIdx.y;
    const int nplanes = (seg == 0) ? 1 : (seg == 1 ? 3 : 5);
    const int stride  = nplanes;
    const int roff    = (seg == 0) ? 0 : (seg == 1 ? 64 : 256);
    const int woff    = (seg == 0) ? 0 : (seg == 1 ? 64 : 256);
    const float* W    = (seg == 0) ? w0 : (seg == 1 ? w1 : w2);

    // split W into smem: pairs along k, ws=72
    for (int i = t; i < 2048; i += 256) {
        int k2 = i >> 6, n = i & 63;
        uint2 p = split_pair(W[(2 * k2) * 64 + n], W[(2 * k2 + 1) * 64 + n]);
        sWd[k2 * 72 + n] = p.x;
        sWd[2304 + k2 * 72 + n] = p.y;
    }
    __syncthreads();

    const int row0 = blockIdx.x * 128 + warp * 16 + g;
    const int row1 = row0 + 8;
    const bool ok0 = (row0 < N_NODES), ok1 = (row1 < N_NODES);

    for (int p = 0; p < nplanes; p++) {
        // load + split A-fragments from g_agg
        uint32_t aH[16], aL[16];
        const float* b0 = g_agg + (size_t)(ok0 ? row0 : 0) * 576 + roff + p * 64;
        const float* b1 = g_agg + (size_t)(ok1 ? row1 : 0) * 576 + roff + p * 64;
#pragma unroll
        for (int kt = 0; kt < 4; kt++) {
            float2 f0 = *reinterpret_cast<const float2*>(b0 + kt * 16 + 2 * q);
            float2 f1 = *reinterpret_cast<const float2*>(b1 + kt * 16 + 2 * q);
            float2 f2 = *reinterpret_cast<const float2*>(b0 + kt * 16 + 8 + 2 * q);
            float2 f3 = *reinterpret_cast<const float2*>(b1 + kt * 16 + 8 + 2 * q);
            uint2 p0 = split_pair(f0.x, f0.y);
            uint2 p1 = split_pair(f1.x, f1.y);
            uint2 p2 = split_pair(f2.x, f2.y);
            uint2 p3 = split_pair(f3.x, f3.y);
            aH[kt * 4 + 0] = p0.x; aL[kt * 4 + 0] = p0.y;
            aH[kt * 4 + 1] = p1.x; aL[kt * 4 + 1] = p1.y;
            aH[kt * 4 + 2] = p2.x; aL[kt * 4 + 2] = p2.y;
            aH[kt * 4 + 3] = p3.x; aL[kt * 4 + 3] = p3.y;
        }

        float C[8][4];
        mma_layer_reg(aH, aL, sWd, sWd + 2304, 72, 0, C, lane);

#pragma unroll
        for (int nt = 0; nt < 8; nt++) {
            const int col = nt * 8 + 2 * q;
            if (ok0) {
                out[(size_t)row0 * 576 + woff + col * stride + p]       = C[nt][0] * 0.125f;
                out[(size_t)row0 * 576 + woff + (col + 1) * stride + p] = C[nt][1] * 0.125f;
            }
            if (ok1) {
                out[(size_t)row1 * 576 + woff + col * stride + p]       = C[nt][2] * 0.125f;
                out[(size_t)row1 * 576 + woff + (col + 1) * stride + p] = C[nt][3] * 0.125f;
            }
        }
    }
}

// ---------------- launcher ------------------------------------------------------
extern "C" void kernel_launch(void* const* d_in, const int* in_sizes, int n_in,
                              void* d_out, int out_size) {
    const float* vectors    = (const float*)d_in[0];
    const float* node_feats = (const float*)d_in[1];
    const float* radial     = (const float*)d_in[2];
    const int*   senders    = (const int*)  d_in[3];
    const int*   receivers  = (const int*)  d_in[4];
    const float* w_up       = (const float*)d_in[5];
    const float* mlp_w1     = (const float*)d_in[6];
    const float* mlp_w2     = (const float*)d_in[7];
    const float* mlp_w3     = (const float*)d_in[8];
    const float* mlp_w4     = (const float*)d_in[9];
    const float* w_down0    = (const float*)d_in[10];
    const float* w_down1    = (const float*)d_in[11];
    const float* w_down2    = (const float*)d_in[12];
    float* out = (float*)d_out;

    const int FUSED_SMEM = 22592 * 4;    // 90,368 B  -> 2 CTAs/SM
    cudaFuncSetAttribute(k_fused, cudaFuncAttributeMaxDynamicSharedMemorySize, FUSED_SMEM);

    k_init<<<11879, 256>>>(node_feats, w_up, mlp_w1, mlp_w2, mlp_w3, mlp_w4);
    k_fused<<<2500, 256, FUSED_SMEM>>>(radial, vectors, senders, receivers);
    k_down<<<dim3(157, 3), 256>>>(w_down0, w_down1, w_down2, out);
}